// round 8
// baseline (speedup 1.0000x reference)
#include <cuda_runtime.h>
#include <cstdint>

// AdditiveModel on GB300 — R7: R6 kernel with x-tile smem cut 4KB so the CTA
// really rounds to 72KB (8KB smem granularity!) -> 3 CTAs/SM, 24 warps.
//  - M=2 batches/thread (weight LDS amortized over 64 batches/warp)
//  - regs capped 80 via __launch_bounds__(256,3)
//  - x staged in half-tiles (8 lags), warp-private double buffer,
//    ALTERNATING row pad 10/8 floats: row r at float off (r>>1)*18+(r&1)*10
//    (all cp.async chunks stay 8B-aligned; read conflicts stay 2-way)
//
// Math (folded into smem-staged weights):
//   sigmoid(z) = 0.5*tanh(0.5 z) + 0.5
//   conv1: a = 0.5*(W1m x + b1); t = tanh(a)
//   conv2: c = (0.25 W2) t + (0.25*rowsum(W2) + 0.5 b2); t2 = tanh(c)
//   out   = sum 0.5*w3*t2 + (b3 + 0.5*sum w3)

#define NV 16
#define BB 32768
typedef unsigned long long ull;

__device__ __forceinline__ ull dup2(float x) {
    ull r; asm("mov.b64 %0, {%1, %1};" : "=l"(r) : "f"(x)); return r;
}
__device__ __forceinline__ ull pack2(float lo, float hi) {
    ull r; asm("mov.b64 %0, {%1, %2};" : "=l"(r) : "f"(lo), "f"(hi)); return r;
}
__device__ __forceinline__ void unpack2(ull v, float& lo, float& hi) {
    asm("mov.b64 {%0, %1}, %2;" : "=f"(lo), "=f"(hi) : "l"(v));
}
__device__ __forceinline__ void fma2(ull& d, ull a, ull b) {
    asm("fma.rn.f32x2 %0, %1, %2, %0;" : "+l"(d) : "l"(a), "l"(b));
}
__device__ __forceinline__ float tanh_fast(float x) {
    float t; asm("tanh.approx.f32 %0, %1;" : "=f"(t) : "f"(x)); return t;
}

// dynamic smem (floats):
//   sX[8 warps][2 halfbuf][576]   36864 B   (64 rows, alternating pad 10/8)
//   sW1p[2048] ull  16384 B   ([j][l][hp] pairs, 0.5*mask folded)
//   sW2p[2048] ull  16384 B   ([j][h][kp] pairs, 0.25 folded)
//   sB1p/sB2p/sW3p[128] ull   3072 B
//   sOutC  16 B                 total 72736 B -> rounds to 72KB -> 3 CTAs/SM
#define SMEM_BYTES (36864 + 16384 + 16384 + 1024 + 1024 + 1024 + 16)

__global__ __launch_bounds__(256, 3)
void additive_model_kernel(const float* __restrict__ x,
                           const int*   __restrict__ causal,
                           const float* __restrict__ W1,
                           const float* __restrict__ b1,
                           const float* __restrict__ W2,
                           const float* __restrict__ b2,
                           const float* __restrict__ W3,
                           const float* __restrict__ b3,
                           float* __restrict__ out)
{
    extern __shared__ float smem[];
    float* sXall = smem;                          // 8 * 2 * 576 = 9216 floats
    ull*   sW1p  = (ull*)(smem + 9216);           // 2048
    ull*   sW2p  = sW1p + 2048;
    ull*   sB1p  = sW2p + 2048;
    ull*   sB2p  = sB1p + 128;
    ull*   sW3p  = sB2p + 128;
    float* sOutC = (float*)(sW3p + 128);

    const int v    = blockIdx.x & 15;
    const int bblk = blockIdx.x >> 4;
    const int tid  = threadIdx.x;
    const int wid  = tid >> 5;
    const int lane = tid & 31;
    const int g0   = v * 16;

    // ---- stage weights (pre-paired, scales folded) ----
    #pragma unroll
    for (int i = 0; i < 8; ++i) {
        const int e  = tid + i * 256;          // 0..2047
        const int j  = e >> 7;
        const int m2 = (e >> 3) & 15;          // l for W1, h for W2
        const int p  = e & 7;                  // hp / kp
        const int g  = g0 + j;
        const float ms = (causal[g * 16 + m2] != 0) ? 0.5f : 0.0f;
        sW1p[e] = pack2(ms * W1[(g * 16 + 2 * p) * 16 + m2],
                        ms * W1[(g * 16 + 2 * p + 1) * 16 + m2]);
        sW2p[e] = pack2(0.25f * W2[g * 256 + (2 * p) * 16 + m2],
                        0.25f * W2[g * 256 + (2 * p + 1) * 16 + m2]);
    }
    if (tid < 128) {
        const int j = tid >> 3, p = tid & 7;
        const int g = g0 + j;
        sB1p[tid] = pack2(0.5f * b1[g * 16 + 2 * p], 0.5f * b1[g * 16 + 2 * p + 1]);
        float s0 = 0.f, s1 = 0.f;
        #pragma unroll
        for (int h = 0; h < 16; ++h) {
            s0 += W2[g * 256 + (2 * p) * 16 + h];
            s1 += W2[g * 256 + (2 * p + 1) * 16 + h];
        }
        sB2p[tid] = pack2(0.25f * s0 + 0.5f * b2[g * 16 + 2 * p],
                          0.25f * s1 + 0.5f * b2[g * 16 + 2 * p + 1]);
        sW3p[tid] = pack2(0.5f * W3[v * 256 + j * 16 + 2 * p],
                          0.5f * W3[v * 256 + j * 16 + 2 * p + 1]);
    }
    if (tid == 0) {
        float c = b3[v];
        #pragma unroll 1
        for (int m = 0; m < 256; ++m) c += 0.5f * W3[v * 256 + m];
        *sOutC = c;
    }
    __syncthreads();   // only CTA barrier

    // ---- warp-private x staging: warp owns 64 batches, half-tile double buffer ----
    // row r lives at float offset (r>>1)*18 + (r&1)*10 within a 576-float half-buffer
    const float* xw = x + (size_t)(bblk * 512 + wid * 64) * 4096 + g0 * 16;
    float* bufA = sXall + wid * 1152;      // half-buffer A (576 floats)
    float* bufB = bufA + 576;              // half-buffer B

    // per-lane staging map: 8 chunks of 8B per half-tile, rows srow0 + 8i
    const int srow0 = lane >> 2;           // 0..7
    const int soff  = (lane & 3) * 2;      // float offset 0,2,4,6 within 8-float half-row
    const int dsto  = (srow0 >> 1) * 18 + (srow0 & 1) * 10 + soff;
    const float* xsrc = xw + (size_t)srow0 * 4096 + soff;   // + j*16 + h*8 + i*8*4096
    const uint32_t dA = (uint32_t)__cvta_generic_to_shared(bufA + dsto);
    const uint32_t dB = (uint32_t)__cvta_generic_to_shared(bufB + dsto);

    #define STAGE_HALF(dst, j_, h_)                                                   \
        do {                                                                          \
            const float* _s = xsrc + (j_) * 16 + (h_) * 8;                            \
            _Pragma("unroll")                                                         \
            for (int _i = 0; _i < 8; ++_i) {                                          \
                asm volatile("cp.async.ca.shared.global [%0], [%1], 8;"               \
                             :: "r"((dst) + _i * (4 * 18 * 4)),                       \
                                "l"(_s + (size_t)_i * 8 * 4096));                     \
            }                                                                         \
            asm volatile("cp.async.commit_group;");                                   \
        } while (0)

    // prologue: both halves of tile j=0
    STAGE_HALF(dA, 0, 0);
    STAGE_HALF(dB, 0, 1);

    // this thread's read rows: lane and lane+32 (+32 rows = +16*18 floats)
    const int roff = (lane >> 1) * 18 + (lane & 1) * 10;

    ull sp0 = 0ull, sp1 = 0ull;

    #pragma unroll 1
    for (int j = 0; j < 16; ++j) {
        ull a0[8], a1[8];
        #pragma unroll
        for (int hp = 0; hp < 8; ++hp) { a0[hp] = sB1p[j * 8 + hp]; a1[hp] = a0[hp]; }

        const ulonglong2* w1 = (const ulonglong2*)(sW1p + j * 128);

        // ---- conv1 over two halves ----
        #pragma unroll
        for (int h = 0; h < 2; ++h) {
            asm volatile("cp.async.wait_group 1;" ::: "memory");
            __syncwarp();
            const float* xb0 = (h ? bufB : bufA) + roff;
            const float* xb1 = xb0 + 16 * 18;   // row lane+32

            #pragma unroll
            for (int l2 = 0; l2 < 4; ++l2) {
                const int l = h * 8 + l2 * 2;
                const float2 xa = *(const float2*)(xb0 + l2 * 2);
                const float2 xb = *(const float2*)(xb1 + l2 * 2);
                ulonglong2 p0 = w1[l * 4 + 0], p1 = w1[l * 4 + 1],
                           p2 = w1[l * 4 + 2], p3 = w1[l * 4 + 3];
                ull da = dup2(xa.x), db = dup2(xb.x);
                fma2(a0[0], p0.x, da); fma2(a1[0], p0.x, db);
                fma2(a0[1], p0.y, da); fma2(a1[1], p0.y, db);
                fma2(a0[2], p1.x, da); fma2(a1[2], p1.x, db);
                fma2(a0[3], p1.y, da); fma2(a1[3], p1.y, db);
                fma2(a0[4], p2.x, da); fma2(a1[4], p2.x, db);
                fma2(a0[5], p2.y, da); fma2(a1[5], p2.y, db);
                fma2(a0[6], p3.x, da); fma2(a1[6], p3.x, db);
                fma2(a0[7], p3.y, da); fma2(a1[7], p3.y, db);
                p0 = w1[(l + 1) * 4 + 0]; p1 = w1[(l + 1) * 4 + 1];
                p2 = w1[(l + 1) * 4 + 2]; p3 = w1[(l + 1) * 4 + 3];
                da = dup2(xa.y); db = dup2(xb.y);
                fma2(a0[0], p0.x, da); fma2(a1[0], p0.x, db);
                fma2(a0[1], p0.y, da); fma2(a1[1], p0.y, db);
                fma2(a0[2], p1.x, da); fma2(a1[2], p1.x, db);
                fma2(a0[3], p1.y, da); fma2(a1[3], p1.y, db);
                fma2(a0[4], p2.x, da); fma2(a1[4], p2.x, db);
                fma2(a0[5], p2.y, da); fma2(a1[5], p2.y, db);
                fma2(a0[6], p3.x, da); fma2(a1[6], p3.x, db);
                fma2(a0[7], p3.y, da); fma2(a1[7], p3.y, db);
            }

            // this half-buffer is now free: prefetch the same half of tile j+1
            if (j < 15) STAGE_HALF(h ? dB : dA, j + 1, h);
        }

        // ---- tanh in place: a[] becomes packed tanh pairs ----
        #pragma unroll
        for (int hp = 0; hp < 8; ++hp) {
            float lo, hi;
            unpack2(a0[hp], lo, hi); a0[hp] = pack2(tanh_fast(lo), tanh_fast(hi));
            unpack2(a1[hp], lo, hi); a1[hp] = pack2(tanh_fast(lo), tanh_fast(hi));
        }

        // ---- conv2: c = (0.25 W2) t + c0 ----
        ull c0[8], c1[8];
        #pragma unroll
        for (int kp = 0; kp < 8; ++kp) { c0[kp] = sB2p[j * 8 + kp]; c1[kp] = c0[kp]; }

        const ulonglong2* w2 = (const ulonglong2*)(sW2p + j * 128);
        #pragma unroll
        for (int hp = 0; hp < 8; ++hp) {
            float s0lo, s0hi, s1lo, s1hi;
            unpack2(a0[hp], s0lo, s0hi);
            unpack2(a1[hp], s1lo, s1hi);
            {   // h = 2*hp
                const int h = 2 * hp;
                const ulonglong2 q0 = w2[h * 4 + 0], q1 = w2[h * 4 + 1],
                                 q2 = w2[h * 4 + 2], q3 = w2[h * 4 + 3];
                const ull da = dup2(s0lo), db = dup2(s1lo);
                fma2(c0[0], q0.x, da); fma2(c1[0], q0.x, db);
                fma2(c0[1], q0.y, da); fma2(c1[1], q0.y, db);
                fma2(c0[2], q1.x, da); fma2(c1[2], q1.x, db);
                fma2(c0[3], q1.y, da); fma2(c1[3], q1.y, db);
                fma2(c0[4], q2.x, da); fma2(c1[4], q2.x, db);
                fma2(c0[5], q2.y, da); fma2(c1[5], q2.y, db);
                fma2(c0[6], q3.x, da); fma2(c1[6], q3.x, db);
                fma2(c0[7], q3.y, da); fma2(c1[7], q3.y, db);
            }
            {   // h = 2*hp + 1
                const int h = 2 * hp + 1;
                const ulonglong2 q0 = w2[h * 4 + 0], q1 = w2[h * 4 + 1],
                                 q2 = w2[h * 4 + 2], q3 = w2[h * 4 + 3];
                const ull da = dup2(s0hi), db = dup2(s1hi);
                fma2(c0[0], q0.x, da); fma2(c1[0], q0.x, db);
                fma2(c0[1], q0.y, da); fma2(c1[1], q0.y, db);
                fma2(c0[2], q1.x, da); fma2(c1[2], q1.x, db);
                fma2(c0[3], q1.y, da); fma2(c1[3], q1.y, db);
                fma2(c0[4], q2.x, da); fma2(c1[4], q2.x, db);
                fma2(c0[5], q2.y, da); fma2(c1[5], q2.y, db);
                fma2(c0[6], q3.x, da); fma2(c1[6], q3.x, db);
                fma2(c0[7], q3.y, da); fma2(c1[7], q3.y, db);
            }
        }

        // ---- epilogue: sp += (0.5 w3) * tanh(c) ----
        #pragma unroll
        for (int kp = 0; kp < 8; ++kp) {
            const ull w3 = sW3p[j * 8 + kp];
            float lo, hi;
            unpack2(c0[kp], lo, hi);
            fma2(sp0, w3, pack2(tanh_fast(lo), tanh_fast(hi)));
            unpack2(c1[kp], lo, hi);
            fma2(sp1, w3, pack2(tanh_fast(lo), tanh_fast(hi)));
        }
    }
    #undef STAGE_HALF

    const float outC = *sOutC;
    const int b0 = bblk * 512 + wid * 64 + lane;
    float lo, hi;
    unpack2(sp0, lo, hi);
    out[(size_t)b0 * NV + v] = lo + hi + outC;
    unpack2(sp1, lo, hi);
    out[(size_t)(b0 + 32) * NV + v] = lo + hi + outC;
}

extern "C" void kernel_launch(void* const* d_in, const int* in_sizes, int n_in,
                              void* d_out, int out_size)
{
    const float* x      = (const float*)d_in[0];
    const int*   causal = (const int*)  d_in[1];
    const float* W1     = (const float*)d_in[2];
    const float* b1     = (const float*)d_in[3];
    const float* W2     = (const float*)d_in[4];
    const float* b2     = (const float*)d_in[5];
    const float* W3     = (const float*)d_in[6];
    const float* b3     = (const float*)d_in[7];
    float* out = (float*)d_out;

    static int configured = 0;
    if (!configured) {
        cudaFuncSetAttribute(additive_model_kernel,
                             cudaFuncAttributeMaxDynamicSharedMemorySize, SMEM_BYTES);
        configured = 1;
    }

    dim3 grid((BB / 512) * NV);   // 64 batch blocks * 16 variables = 1024 CTAs
    additive_model_kernel<<<grid, 256, SMEM_BYTES>>>(x, causal, W1, b1, W2, b2, W3, b3, out);
}

// round 10
// speedup vs baseline: 1.1804x; 1.1804x over previous
#include <cuda_runtime.h>
#include <cstdint>

// AdditiveModel on GB300 — R8: R6 structure (best, 279us) with the accidental
// 80-reg cap removed: __launch_bounds__(256,2) -> ptxas gets up to 128 regs to
// hoist weight LDS and deepen FFMA independence. Occupancy unchanged (smem
// rounds to 80KB -> 2 CTAs regardless).
//  - M=2 batches/thread (weight LDS amortized over 64 batches/warp)
//  - x staged in half-tiles (8 lags), warp-private cp.async double buffer
//
// Math (folded into smem-staged weights):
//   sigmoid(z) = 0.5*tanh(0.5 z) + 0.5
//   conv1: a = 0.5*(W1m x + b1); t = tanh(a)
//   conv2: c = (0.25 W2) t + (0.25*rowsum(W2) + 0.5 b2); t2 = tanh(c)
//   out   = sum 0.5*w3*t2 + (b3 + 0.5*sum w3)

#define NV 16
#define BB 32768
typedef unsigned long long ull;

__device__ __forceinline__ ull dup2(float x) {
    ull r; asm("mov.b64 %0, {%1, %1};" : "=l"(r) : "f"(x)); return r;
}
__device__ __forceinline__ ull pack2(float lo, float hi) {
    ull r; asm("mov.b64 %0, {%1, %2};" : "=l"(r) : "f"(lo), "f"(hi)); return r;
}
__device__ __forceinline__ void unpack2(ull v, float& lo, float& hi) {
    asm("mov.b64 {%0, %1}, %2;" : "=f"(lo), "=f"(hi) : "l"(v));
}
__device__ __forceinline__ void fma2(ull& d, ull a, ull b) {
    asm("fma.rn.f32x2 %0, %1, %2, %0;" : "+l"(d) : "l"(a), "l"(b));
}
__device__ __forceinline__ float tanh_fast(float x) {
    float t; asm("tanh.approx.f32 %0, %1;" : "=f"(t) : "f"(x)); return t;
}

// dynamic smem (floats):
//   sX[8 warps][2 halfbuf][64 rows][10]  40960 B  (pad-10 rows)
//   sW1p[2048] ull  16384 B   ([j][l][hp] pairs, 0.5*mask folded)
//   sW2p[2048] ull  16384 B   ([j][h][kp] pairs, 0.25 folded)
//   sB1p/sB2p/sW3p[128] ull   3072 B
//   sOutC  16 B                          total 76816 B -> 80KB -> 2 CTAs/SM
#define SMEM_BYTES (40960 + 16384 + 16384 + 1024 + 1024 + 1024 + 16)

__global__ __launch_bounds__(256, 2)
void additive_model_kernel(const float* __restrict__ x,
                           const int*   __restrict__ causal,
                           const float* __restrict__ W1,
                           const float* __restrict__ b1,
                           const float* __restrict__ W2,
                           const float* __restrict__ b2,
                           const float* __restrict__ W3,
                           const float* __restrict__ b3,
                           float* __restrict__ out)
{
    extern __shared__ float smem[];
    float* sXall = smem;                          // 8 * 2 * 640 = 10240 floats
    ull*   sW1p  = (ull*)(smem + 10240);          // 2048
    ull*   sW2p  = sW1p + 2048;
    ull*   sB1p  = sW2p + 2048;
    ull*   sB2p  = sB1p + 128;
    ull*   sW3p  = sB2p + 128;
    float* sOutC = (float*)(sW3p + 128);

    const int v    = blockIdx.x & 15;
    const int bblk = blockIdx.x >> 4;
    const int tid  = threadIdx.x;
    const int wid  = tid >> 5;
    const int lane = tid & 31;
    const int g0   = v * 16;

    // ---- stage weights (pre-paired, scales folded) ----
    #pragma unroll
    for (int i = 0; i < 8; ++i) {
        const int e  = tid + i * 256;          // 0..2047
        const int j  = e >> 7;
        const int m2 = (e >> 3) & 15;          // l for W1, h for W2
        const int p  = e & 7;                  // hp / kp
        const int g  = g0 + j;
        const float ms = (causal[g * 16 + m2] != 0) ? 0.5f : 0.0f;
        sW1p[e] = pack2(ms * W1[(g * 16 + 2 * p) * 16 + m2],
                        ms * W1[(g * 16 + 2 * p + 1) * 16 + m2]);
        sW2p[e] = pack2(0.25f * W2[g * 256 + (2 * p) * 16 + m2],
                        0.25f * W2[g * 256 + (2 * p + 1) * 16 + m2]);
    }
    if (tid < 128) {
        const int j = tid >> 3, p = tid & 7;
        const int g = g0 + j;
        sB1p[tid] = pack2(0.5f * b1[g * 16 + 2 * p], 0.5f * b1[g * 16 + 2 * p + 1]);
        float s0 = 0.f, s1 = 0.f;
        #pragma unroll
        for (int h = 0; h < 16; ++h) {
            s0 += W2[g * 256 + (2 * p) * 16 + h];
            s1 += W2[g * 256 + (2 * p + 1) * 16 + h];
        }
        sB2p[tid] = pack2(0.25f * s0 + 0.5f * b2[g * 16 + 2 * p],
                          0.25f * s1 + 0.5f * b2[g * 16 + 2 * p + 1]);
        sW3p[tid] = pack2(0.5f * W3[v * 256 + j * 16 + 2 * p],
                          0.5f * W3[v * 256 + j * 16 + 2 * p + 1]);
    }
    if (tid == 0) {
        float c = b3[v];
        #pragma unroll 1
        for (int m = 0; m < 256; ++m) c += 0.5f * W3[v * 256 + m];
        *sOutC = c;
    }
    __syncthreads();   // only CTA barrier

    // ---- warp-private x staging: warp owns 64 batches, half-tile double buffer ----
    const float* xw = x + (size_t)(bblk * 512 + wid * 64) * 4096 + g0 * 16;
    float* bufA = sXall + wid * 1280;      // half-buffer A (640 floats)
    float* bufB = bufA + 640;              // half-buffer B

    // per-lane staging map: 8 chunks of 8B per half-tile
    const int srow0 = lane >> 2;           // 0..7
    const int soff  = (lane & 3) * 2;      // float offset 0,2,4,6 within 8-float half-row
    const float* xsrc = xw + (size_t)srow0 * 4096 + soff;   // + j*16 + h*8 + i*8*4096
    const uint32_t dA = (uint32_t)__cvta_generic_to_shared(bufA + srow0 * 10 + soff);
    const uint32_t dB = (uint32_t)__cvta_generic_to_shared(bufB + srow0 * 10 + soff);

    #define STAGE_HALF(dst, j_, h_)                                                   \
        do {                                                                          \
            const float* _s = xsrc + (j_) * 16 + (h_) * 8;                            \
            _Pragma("unroll")                                                         \
            for (int _i = 0; _i < 8; ++_i) {                                          \
                asm volatile("cp.async.ca.shared.global [%0], [%1], 8;"               \
                             :: "r"((dst) + _i * (8 * 10 * 4)),                       \
                                "l"(_s + (size_t)_i * 8 * 4096));                     \
            }                                                                         \
            asm volatile("cp.async.commit_group;");                                   \
        } while (0)

    // prologue: both halves of tile j=0
    STAGE_HALF(dA, 0, 0);
    STAGE_HALF(dB, 0, 1);

    ull sp0 = 0ull, sp1 = 0ull;

    #pragma unroll 1
    for (int j = 0; j < 16; ++j) {
        ull a0[8], a1[8];
        #pragma unroll
        for (int hp = 0; hp < 8; ++hp) { a0[hp] = sB1p[j * 8 + hp]; a1[hp] = a0[hp]; }

        const ulonglong2* w1 = (const ulonglong2*)(sW1p + j * 128);

        // ---- conv1 over two halves ----
        #pragma unroll
        for (int h = 0; h < 2; ++h) {
            asm volatile("cp.async.wait_group 1;" ::: "memory");
            __syncwarp();
            const float* xb0 = (h ? bufB : bufA) + lane * 10;
            const float* xb1 = (h ? bufB : bufA) + (lane + 32) * 10;

            #pragma unroll
            for (int l2 = 0; l2 < 4; ++l2) {
                const int l = h * 8 + l2 * 2;
                const float2 xa = *(const float2*)(xb0 + l2 * 2);
                const float2 xb = *(const float2*)(xb1 + l2 * 2);
                ulonglong2 p0 = w1[l * 4 + 0], p1 = w1[l * 4 + 1],
                           p2 = w1[l * 4 + 2], p3 = w1[l * 4 + 3];
                ull da = dup2(xa.x), db = dup2(xb.x);
                fma2(a0[0], p0.x, da); fma2(a1[0], p0.x, db);
                fma2(a0[1], p0.y, da); fma2(a1[1], p0.y, db);
                fma2(a0[2], p1.x, da); fma2(a1[2], p1.x, db);
                fma2(a0[3], p1.y, da); fma2(a1[3], p1.y, db);
                fma2(a0[4], p2.x, da); fma2(a1[4], p2.x, db);
                fma2(a0[5], p2.y, da); fma2(a1[5], p2.y, db);
                fma2(a0[6], p3.x, da); fma2(a1[6], p3.x, db);
                fma2(a0[7], p3.y, da); fma2(a1[7], p3.y, db);
                p0 = w1[(l + 1) * 4 + 0]; p1 = w1[(l + 1) * 4 + 1];
                p2 = w1[(l + 1) * 4 + 2]; p3 = w1[(l + 1) * 4 + 3];
                da = dup2(xa.y); db = dup2(xb.y);
                fma2(a0[0], p0.x, da); fma2(a1[0], p0.x, db);
                fma2(a0[1], p0.y, da); fma2(a1[1], p0.y, db);
                fma2(a0[2], p1.x, da); fma2(a1[2], p1.x, db);
                fma2(a0[3], p1.y, da); fma2(a1[3], p1.y, db);
                fma2(a0[4], p2.x, da); fma2(a1[4], p2.x, db);
                fma2(a0[5], p2.y, da); fma2(a1[5], p2.y, db);
                fma2(a0[6], p3.x, da); fma2(a1[6], p3.x, db);
                fma2(a0[7], p3.y, da); fma2(a1[7], p3.y, db);
            }

            // this half-buffer is now free: prefetch the same half of tile j+1
            if (j < 15) STAGE_HALF(h ? dB : dA, j + 1, h);
        }

        // ---- tanh in place: a[] becomes packed tanh pairs ----
        #pragma unroll
        for (int hp = 0; hp < 8; ++hp) {
            float lo, hi;
            unpack2(a0[hp], lo, hi); a0[hp] = pack2(tanh_fast(lo), tanh_fast(hi));
            unpack2(a1[hp], lo, hi); a1[hp] = pack2(tanh_fast(lo), tanh_fast(hi));
        }

        // ---- conv2: c = (0.25 W2) t + c0 ----
        ull c0[8], c1[8];
        #pragma unroll
        for (int kp = 0; kp < 8; ++kp) { c0[kp] = sB2p[j * 8 + kp]; c1[kp] = c0[kp]; }

        const ulonglong2* w2 = (const ulonglong2*)(sW2p + j * 128);
        #pragma unroll
        for (int hp = 0; hp < 8; ++hp) {
            float s0lo, s0hi, s1lo, s1hi;
            unpack2(a0[hp], s0lo, s0hi);
            unpack2(a1[hp], s1lo, s1hi);
            {   // h = 2*hp
                const int h = 2 * hp;
                const ulonglong2 q0 = w2[h * 4 + 0], q1 = w2[h * 4 + 1],
                                 q2 = w2[h * 4 + 2], q3 = w2[h * 4 + 3];
                const ull da = dup2(s0lo), db = dup2(s1lo);
                fma2(c0[0], q0.x, da); fma2(c1[0], q0.x, db);
                fma2(c0[1], q0.y, da); fma2(c1[1], q0.y, db);
                fma2(c0[2], q1.x, da); fma2(c1[2], q1.x, db);
                fma2(c0[3], q1.y, da); fma2(c1[3], q1.y, db);
                fma2(c0[4], q2.x, da); fma2(c1[4], q2.x, db);
                fma2(c0[5], q2.y, da); fma2(c1[5], q2.y, db);
                fma2(c0[6], q3.x, da); fma2(c1[6], q3.x, db);
                fma2(c0[7], q3.y, da); fma2(c1[7], q3.y, db);
            }
            {   // h = 2*hp + 1
                const int h = 2 * hp + 1;
                const ulonglong2 q0 = w2[h * 4 + 0], q1 = w2[h * 4 + 1],
                                 q2 = w2[h * 4 + 2], q3 = w2[h * 4 + 3];
                const ull da = dup2(s0hi), db = dup2(s1hi);
                fma2(c0[0], q0.x, da); fma2(c1[0], q0.x, db);
                fma2(c0[1], q0.y, da); fma2(c1[1], q0.y, db);
                fma2(c0[2], q1.x, da); fma2(c1[2], q1.x, db);
                fma2(c0[3], q1.y, da); fma2(c1[3], q1.y, db);
                fma2(c0[4], q2.x, da); fma2(c1[4], q2.x, db);
                fma2(c0[5], q2.y, da); fma2(c1[5], q2.y, db);
                fma2(c0[6], q3.x, da); fma2(c1[6], q3.x, db);
                fma2(c0[7], q3.y, da); fma2(c1[7], q3.y, db);
            }
        }

        // ---- epilogue: sp += (0.5 w3) * tanh(c) ----
        #pragma unroll
        for (int kp = 0; kp < 8; ++kp) {
            const ull w3 = sW3p[j * 8 + kp];
            float lo, hi;
            unpack2(c0[kp], lo, hi);
            fma2(sp0, w3, pack2(tanh_fast(lo), tanh_fast(hi)));
            unpack2(c1[kp], lo, hi);
            fma2(sp1, w3, pack2(tanh_fast(lo), tanh_fast(hi)));
        }
    }
    #undef STAGE_HALF

    const float outC = *sOutC;
    const int b0 = bblk * 512 + wid * 64 + lane;
    float lo, hi;
    unpack2(sp0, lo, hi);
    out[(size_t)b0 * NV + v] = lo + hi + outC;
    unpack2(sp1, lo, hi);
    out[(size_t)(b0 + 32) * NV + v] = lo + hi + outC;
}

extern "C" void kernel_launch(void* const* d_in, const int* in_sizes, int n_in,
                              void* d_out, int out_size)
{
    const float* x      = (const float*)d_in[0];
    const int*   causal = (const int*)  d_in[1];
    const float* W1     = (const float*)d_in[2];
    const float* b1     = (const float*)d_in[3];
    const float* W2     = (const float*)d_in[4];
    const float* b2     = (const float*)d_in[5];
    const float* W3     = (const float*)d_in[6];
    const float* b3     = (const float*)d_in[7];
    float* out = (float*)d_out;

    static int configured = 0;
    if (!configured) {
        cudaFuncSetAttribute(additive_model_kernel,
                             cudaFuncAttributeMaxDynamicSharedMemorySize, SMEM_BYTES);
        configured = 1;
    }

    dim3 grid((BB / 512) * NV);   // 64 batch blocks * 16 variables = 1024 CTAs
    additive_model_kernel<<<grid, 256, SMEM_BYTES>>>(x, causal, W1, b1, W2, b2, W3, b3, out);
}